// round 9
// baseline (speedup 1.0000x reference)
#include <cuda_runtime.h>
#include <cuda_fp16.h>
#include <cstdint>
#include <math.h>

#define B_ 2
#define E_ 32768
#define D_ 512
#define G_ 2048

// ---------------- scratch ------------------------------------------------------------
// EV: [m, 0:512] = exp(logit) fp16, [m, 512:1024] = val fp16
__device__ __half g_EV[(size_t)B_ * E_ * 1024];
__device__ __half g_x16[(size_t)B_ * E_ * D_];
__device__ __half g_wstk[1024 * 512];               // [Wg; Wf] fp16
__device__ float  g_bstk[1024];
__device__ __half g_wh[D_ * D_];
__device__ __half g_y16[(size_t)B_ * G_ * D_];
__device__ int    g_cnt[G_], g_start[G_ + 1], g_cursor[G_], g_order[E_];

// ---------------- PTX helpers ---------------------------------------------------------
__device__ __forceinline__ uint32_t smem_u32(const void* p) {
    uint32_t a;
    asm("{ .reg .u64 t; cvta.to.shared.u64 t, %1; cvt.u32.u64 %0, t; }" : "=r"(a) : "l"(p));
    return a;
}
__device__ __forceinline__ void cp16(uint32_t s, const void* g) {
    asm volatile("cp.async.cg.shared.global [%0], [%1], 16;" :: "r"(s), "l"(g));
}
#define CP_COMMIT() asm volatile("cp.async.commit_group;" ::: "memory")
#define CP_WAIT(n)  asm volatile("cp.async.wait_group %0;" :: "n"(n) : "memory")

__device__ __forceinline__ void ldsm4(uint32_t* r, uint32_t addr) {
    asm volatile("ldmatrix.sync.aligned.m8n8.x4.shared.b16 {%0,%1,%2,%3}, [%4];"
                 : "=r"(r[0]), "=r"(r[1]), "=r"(r[2]), "=r"(r[3]) : "r"(addr));
}
__device__ __forceinline__ void mma_f16(float* c, const uint32_t* a, const uint32_t* b) {
    asm volatile(
        "mma.sync.aligned.m16n8k16.row.col.f32.f16.f16.f32 "
        "{%0,%1,%2,%3}, {%4,%5,%6,%7}, {%8,%9}, {%0,%1,%2,%3};"
        : "+f"(c[0]), "+f"(c[1]), "+f"(c[2]), "+f"(c[3])
        : "r"(a[0]), "r"(a[1]), "r"(a[2]), "r"(a[3]), "r"(b[0]), "r"(b[1]));
}

// ---------------- fused prep: x cvt + weight cvts + bias + histogram ---------------------
// blocks [0, 32768)        : x -> fp16 (256 float4 per block)
// blocks [32768, 33536)    : Wg/Wf/Wh -> fp16 (256 blocks each)
// block  33536             : bias stack
// blocks [33537, 33665)    : histogram of ix
__global__ void prep_k(const float* __restrict__ x,
                       const float* __restrict__ Wg, const float* __restrict__ Wf,
                       const float* __restrict__ Wh,
                       const float* __restrict__ bg, const float* __restrict__ bf,
                       const int* __restrict__ ix) {
    int bid = blockIdx.x, t = threadIdx.x;
    if (bid < 32768) {
        size_t i = (size_t)bid * 256 + t;      // float4 index into x
        float4 f = ((const float4*)x)[i];
        ((__half2*)g_x16)[2 * i]     = __halves2half2(__float2half(f.x), __float2half(f.y));
        ((__half2*)g_x16)[2 * i + 1] = __halves2half2(__float2half(f.z), __float2half(f.w));
    } else if (bid < 33536) {
        int wb = bid - 32768;
        const float* src = (wb < 256) ? Wg : ((wb < 512) ? Wf : Wh);
        __half* dst = (wb < 256) ? g_wstk : ((wb < 512) ? (g_wstk + 512 * 512) : g_wh);
        int i = (wb & 255) * 256 + t;          // float4 index, 65536 per matrix
        float4 f = ((const float4*)src)[i];
        ((__half2*)dst)[2 * i]     = __halves2half2(__float2half(f.x), __float2half(f.y));
        ((__half2*)dst)[2 * i + 1] = __halves2half2(__float2half(f.z), __float2half(f.w));
    } else if (bid == 33536) {
        for (int q = t; q < 1024; q += 256)
            g_bstk[q] = (q < 512) ? bg[q] : bf[q - 512];
    } else {
        int e = (bid - 33537) * 256 + t;
        if (e < E_) atomicAdd(&g_cnt[ix[e]], 1);
    }
}

// ---------------- CSR scan + scatter ------------------------------------------------------
__global__ void scan_k() {   // 1 block, 1024 threads, 2 elems each; self-zeros g_cnt
    __shared__ int ps[1024];
    int t = threadIdx.x;
    int c0 = g_cnt[2 * t], c1 = g_cnt[2 * t + 1];
    g_cnt[2 * t] = 0; g_cnt[2 * t + 1] = 0;          // reset for next graph replay
    ps[t] = c0 + c1;
    __syncthreads();
#pragma unroll
    for (int off = 1; off < 1024; off <<= 1) {
        int v = (t >= off) ? ps[t - off] : 0;
        __syncthreads();
        ps[t] += v;
        __syncthreads();
    }
    int excl = (t > 0) ? ps[t - 1] : 0;
    g_start[2 * t] = excl;          g_cursor[2 * t] = excl;
    g_start[2 * t + 1] = excl + c0; g_cursor[2 * t + 1] = excl + c0;
    if (t == 1023) g_start[2048] = ps[1023];
}
__global__ void scatter_k(const int* __restrict__ ix) {
    int e = threadIdx.x + blockIdx.x * blockDim.x;
    if (e >= E_) return;
    int idx = atomicAdd(&g_cursor[ix[e]], 1);
    g_order[idx] = e;
}

// ---------------- fp16 GEMM on mma.sync, 4-stage pipeline --------------------------------
// MODE 1: C fp16 (EV); cols < 512 get exp() applied (logits), rest plain (vals)
// MODE 2: fused output scatter: row m = b*G+g, write (v+bias) to out[b,e,:] for all edges
#define PITCH 80
#define ABUF  10240            // 128 rows * 80
#define BUFSZ 30720            // A + B per stage
#define NSTAGE 4
#define SMEM_GEMM (NSTAGE * BUFSZ)  // 122880

template<int MODE>
__global__ __launch_bounds__(512, 1)
void gemm16(const __half* __restrict__ A, const __half* __restrict__ Bw,
            const float* __restrict__ bias, void* __restrict__ Cout, int ldc) {
    extern __shared__ char smem[];
    const uint32_t sb = smem_u32(smem);
    const int tid = threadIdx.x, lane = tid & 31, wid = tid >> 5;
    const int wm = wid >> 2, wn = wid & 3;
    const int m0 = blockIdx.y * 128, n0 = blockIdx.x * 256;

    float acc[2][8][4];
#pragma unroll
    for (int mt = 0; mt < 2; mt++)
#pragma unroll
        for (int nt = 0; nt < 8; nt++)
#pragma unroll
            for (int q = 0; q < 4; q++) acc[mt][nt][q] = 0.0f;

    auto load_buf = [&](int kc, int buf) {
        const int k0 = kc * 32;
        const uint32_t bb = sb + buf * BUFSZ;
#pragma unroll
        for (int t = 0; t < 3; t++) {
            int q = tid + t * 512;
            const __half* src;
            uint32_t base;
            int qq;
            if (q < 512) { src = A;  base = 0;    qq = q; }
            else         { src = Bw; base = ABUF; qq = q - 512; }
            int row = qq >> 2, c = qq & 3;
            int grow = (q < 512) ? (m0 + row) : (n0 + row);
            cp16(bb + base + (uint32_t)(row * PITCH + c * 16),
                 src + (size_t)grow * 512 + k0 + c * 8);
        }
    };

    load_buf(0, 0); CP_COMMIT();
    load_buf(1, 1); CP_COMMIT();
    load_buf(2, 2); CP_COMMIT();

    const uint32_t a_lane = (uint32_t)((wm * 32 + (lane & 15)) * PITCH + (lane >> 4) * 16);
    const uint32_t b_lane = (uint32_t)((wn * 64 + ((lane >> 4) & 1) * 8 + (lane & 7)) * PITCH +
                                       ((lane >> 3) & 1) * 16);

    for (int kc = 0; kc < 16; kc++) {
        CP_WAIT(2);
        __syncthreads();
        if (kc + 3 < 16) load_buf(kc + 3, (kc + 3) & (NSTAGE - 1));
        CP_COMMIT();

        const uint32_t bb = sb + (kc & (NSTAGE - 1)) * BUFSZ;
#pragma unroll
        for (int ks = 0; ks < 2; ks++) {
            uint32_t ah[2][4], bfr[4][4];
            uint32_t aoff = a_lane + (uint32_t)(ks * 32);
            ldsm4(ah[0], bb + aoff);
            ldsm4(ah[1], bb + aoff + 16 * PITCH);
#pragma unroll
            for (int np = 0; np < 4; np++)
                ldsm4(bfr[np], bb + ABUF + b_lane +
                                  (uint32_t)(np * 16 * PITCH + ks * 32));
#pragma unroll
            for (int np = 0; np < 4; np++) {
                mma_f16(acc[0][2 * np],     ah[0], bfr[np]);
                mma_f16(acc[0][2 * np + 1], ah[0], bfr[np] + 2);
                mma_f16(acc[1][2 * np],     ah[1], bfr[np]);
                mma_f16(acc[1][2 * np + 1], ah[1], bfr[np] + 2);
            }
        }
    }

    // add bias into acc
#pragma unroll
    for (int nt = 0; nt < 8; nt++) {
        int col = n0 + wn * 64 + nt * 8 + (lane & 3) * 2;
        float b0 = bias[col], b1 = bias[col + 1];
#pragma unroll
        for (int mt = 0; mt < 2; mt++) {
            acc[mt][nt][0] += b0; acc[mt][nt][1] += b1;
            acc[mt][nt][2] += b0; acc[mt][nt][3] += b1;
        }
    }

    if (MODE == 1) {
        const bool doexp = (n0 < 512);
#pragma unroll
        for (int mt = 0; mt < 2; mt++) {
            int r0 = m0 + wm * 32 + mt * 16 + (lane >> 2);
#pragma unroll
            for (int nt = 0; nt < 8; nt++) {
                int col = n0 + wn * 64 + nt * 8 + (lane & 3) * 2;
                float v0 = acc[mt][nt][0], v1 = acc[mt][nt][1];
                float v2 = acc[mt][nt][2], v3 = acc[mt][nt][3];
                if (doexp) { v0 = __expf(v0); v1 = __expf(v1); v2 = __expf(v2); v3 = __expf(v3); }
                __half* C = (__half*)Cout;
                *(__half2*)&C[(size_t)r0 * ldc + col]       = __floats2half2_rn(v0, v1);
                *(__half2*)&C[(size_t)(r0 + 8) * ldc + col] = __floats2half2_rn(v2, v3);
            }
        }
    } else {
        // MODE 2: scatter each (b,g) row's 256-col slice to all its edges
        float* out = (float*)Cout;
#pragma unroll
        for (int mt = 0; mt < 2; mt++) {
#pragma unroll
            for (int sub = 0; sub < 2; sub++) {
                int r = m0 + wm * 32 + mt * 16 + sub * 8 + (lane >> 2);
                int b = r >> 11, g = r & 2047;
                int s = g_start[g], ee = g_start[g + 1];
                for (int j = s; j < ee; j++) {
                    int e = g_order[j];
                    float* base = out + ((size_t)b * E_ + e) * 512;
#pragma unroll
                    for (int nt = 0; nt < 8; nt++) {
                        int col = n0 + wn * 64 + nt * 8 + (lane & 3) * 2;
                        *(float2*)&base[col] =
                            make_float2(acc[mt][nt][2 * sub], acc[mt][nt][2 * sub + 1]);
                    }
                }
            }
        }
    }
}

// ---------------- per-group softmax-weighted reduction (fp16 EV input) --------------------
__global__ __launch_bounds__(128)
void segreduce_k() {
    int g = blockIdx.x, b = blockIdx.y;
    int t = threadIdx.x;                 // t covers d = 4t..4t+3
    int s = g_start[g], e_end = g_start[g + 1];

    float4 den = make_float4(0.f, 0.f, 0.f, 0.f);
    float4 num = make_float4(0.f, 0.f, 0.f, 0.f);

    for (int j = s; j < e_end; j++) {
        int e = g_order[j];
        const __half2* row = (const __half2*)(g_EV + ((size_t)b * E_ + e) * 1024);
        __half2 w01 = row[2 * t],       w23 = row[2 * t + 1];
        __half2 v01 = row[256 + 2 * t], v23 = row[256 + 2 * t + 1];
        float2 w0 = __half22float2(w01), w1 = __half22float2(w23);
        float2 x0 = __half22float2(v01), x1 = __half22float2(v23);
        den.x += w0.x; den.y += w0.y; den.z += w1.x; den.w += w1.y;
        num.x += w0.x * x0.x; num.y += w0.y * x0.y;
        num.z += w1.x * x1.x; num.w += w1.y * x1.y;
    }
    float y0 = (den.x > 0.f) ? num.x / den.x : 0.f;
    float y1 = (den.y > 0.f) ? num.y / den.y : 0.f;
    float y2 = (den.z > 0.f) ? num.z / den.z : 0.f;
    float y3 = (den.w > 0.f) ? num.w / den.w : 0.f;

    size_t o2 = ((size_t)b * G_ + g) * 256 + (size_t)t * 2;   // half2 index
    ((__half2*)g_y16)[o2]     = __floats2half2_rn(y0, y1);
    ((__half2*)g_y16)[o2 + 1] = __floats2half2_rn(y2, y3);
}

// ---------------- launcher -----------------------------------------------------------------
extern "C" void kernel_launch(void* const* d_in, const int* in_sizes, int n_in,
                              void* d_out, int out_size) {
    const float* x  = (const float*)d_in[0];
    const int*   ix = (const int*)d_in[1];
    const float* Wf = (const float*)d_in[2];
    const float* bf = (const float*)d_in[3];
    const float* Wg = (const float*)d_in[4];
    const float* bg = (const float*)d_in[5];
    const float* Wh = (const float*)d_in[6];
    const float* bh = (const float*)d_in[7];
    float* out = (float*)d_out;

    __half *x16, *wstk, *wh, *y16, *ev;
    cudaGetSymbolAddress((void**)&x16, g_x16);
    cudaGetSymbolAddress((void**)&wstk, g_wstk);
    cudaGetSymbolAddress((void**)&wh, g_wh);
    cudaGetSymbolAddress((void**)&y16, g_y16);
    cudaGetSymbolAddress((void**)&ev, g_EV);
    float* pbstk; cudaGetSymbolAddress((void**)&pbstk, g_bstk);

    cudaFuncSetAttribute(gemm16<1>, cudaFuncAttributeMaxDynamicSharedMemorySize, SMEM_GEMM);
    cudaFuncSetAttribute(gemm16<2>, cudaFuncAttributeMaxDynamicSharedMemorySize, SMEM_GEMM);

    const int T = 256;

    // launch 0: fused prep (x cvt + weight cvts + bias + histogram)
    prep_k<<<33665, T>>>(x, Wg, Wf, Wh, bg, bf, ix);
    // launch 1-2: CSR scan + scatter
    scan_k<<<1, 1024>>>();
    scatter_k<<<E_ / T, T>>>(ix);
    // launch 3: projections (stacked) -> EV fp16 (exp applied to logit half)
    {
        dim3 grid(4, (B_ * E_) / 128);
        gemm16<1><<<grid, 512, SMEM_GEMM>>>(x16, wstk, pbstk, ev, 1024);
    }
    // launch 4: per-group softmax-weighted reduce -> y16
    {
        dim3 grid(G_, B_);
        segreduce_k<<<grid, 128>>>();
    }
    // launch 5: of = y @ Wh^T + bh, scattered directly to out[b,e,:]
    {
        dim3 grid(2, (B_ * G_) / 128);
        gemm16<2><<<grid, 512, SMEM_GEMM>>>(y16, wh, bh, out, 512);
    }
}

// round 10
// speedup vs baseline: 1.0479x; 1.0479x over previous
#include <cuda_runtime.h>
#include <cuda_fp16.h>
#include <cstdint>
#include <math.h>

#define B_ 2
#define E_ 32768
#define D_ 512
#define G_ 2048

// ---------------- scratch ------------------------------------------------------------
// EV: [m, 0:512] = exp(logit) fp16, [m, 512:1024] = val fp16
__device__ __half g_EV[(size_t)B_ * E_ * 1024];
__device__ __half g_x16[(size_t)B_ * E_ * D_];
__device__ __half g_wstk[1024 * 512];               // [Wg; Wf] fp16
__device__ float  g_bstk[1024];
__device__ __half g_wh[D_ * D_];
__device__ __half g_y16[(size_t)B_ * G_ * D_];
__device__ float  g_of[(size_t)B_ * G_ * D_];
__device__ int    g_cnt[G_], g_start[G_ + 1], g_cursor[G_], g_order[E_];

// ---------------- PTX helpers ---------------------------------------------------------
__device__ __forceinline__ uint32_t smem_u32(const void* p) {
    uint32_t a;
    asm("{ .reg .u64 t; cvta.to.shared.u64 t, %1; cvt.u32.u64 %0, t; }" : "=r"(a) : "l"(p));
    return a;
}
__device__ __forceinline__ void cp16(uint32_t s, const void* g) {
    asm volatile("cp.async.cg.shared.global [%0], [%1], 16;" :: "r"(s), "l"(g));
}
#define CP_COMMIT() asm volatile("cp.async.commit_group;" ::: "memory")
#define CP_WAIT(n)  asm volatile("cp.async.wait_group %0;" :: "n"(n) : "memory")

__device__ __forceinline__ void ldsm4(uint32_t* r, uint32_t addr) {
    asm volatile("ldmatrix.sync.aligned.m8n8.x4.shared.b16 {%0,%1,%2,%3}, [%4];"
                 : "=r"(r[0]), "=r"(r[1]), "=r"(r[2]), "=r"(r[3]) : "r"(addr));
}
__device__ __forceinline__ void mma_f16(float* c, const uint32_t* a, const uint32_t* b) {
    asm volatile(
        "mma.sync.aligned.m16n8k16.row.col.f32.f16.f16.f32 "
        "{%0,%1,%2,%3}, {%4,%5,%6,%7}, {%8,%9}, {%0,%1,%2,%3};"
        : "+f"(c[0]), "+f"(c[1]), "+f"(c[2]), "+f"(c[3])
        : "r"(a[0]), "r"(a[1]), "r"(a[2]), "r"(a[3]), "r"(b[0]), "r"(b[1]));
}

// ---------------- fused prep: x cvt + weight cvts + bias + histogram ---------------------
__global__ void prep_k(const float* __restrict__ x,
                       const float* __restrict__ Wg, const float* __restrict__ Wf,
                       const float* __restrict__ Wh,
                       const float* __restrict__ bg, const float* __restrict__ bf,
                       const int* __restrict__ ix) {
    int bid = blockIdx.x, t = threadIdx.x;
    if (bid < 32768) {
        size_t i = (size_t)bid * 256 + t;      // float4 index into x
        float4 f = ((const float4*)x)[i];
        ((__half2*)g_x16)[2 * i]     = __halves2half2(__float2half(f.x), __float2half(f.y));
        ((__half2*)g_x16)[2 * i + 1] = __halves2half2(__float2half(f.z), __float2half(f.w));
    } else if (bid < 33536) {
        int wb = bid - 32768;
        const float* src = (wb < 256) ? Wg : ((wb < 512) ? Wf : Wh);
        __half* dst = (wb < 256) ? g_wstk : ((wb < 512) ? (g_wstk + 512 * 512) : g_wh);
        int i = (wb & 255) * 256 + t;          // float4 index, 65536 per matrix
        float4 f = ((const float4*)src)[i];
        ((__half2*)dst)[2 * i]     = __halves2half2(__float2half(f.x), __float2half(f.y));
        ((__half2*)dst)[2 * i + 1] = __halves2half2(__float2half(f.z), __float2half(f.w));
    } else if (bid == 33536) {
        for (int q = t; q < 1024; q += 256)
            g_bstk[q] = (q < 512) ? bg[q] : bf[q - 512];
    } else {
        int e = (bid - 33537) * 256 + t;
        if (e < E_) atomicAdd(&g_cnt[ix[e]], 1);
    }
}

// ---------------- CSR scan + scatter ------------------------------------------------------
__global__ void scan_k() {   // 1 block, 1024 threads; self-zeros g_cnt for graph replay
    __shared__ int ps[1024];
    int t = threadIdx.x;
    int c0 = g_cnt[2 * t], c1 = g_cnt[2 * t + 1];
    g_cnt[2 * t] = 0; g_cnt[2 * t + 1] = 0;
    ps[t] = c0 + c1;
    __syncthreads();
#pragma unroll
    for (int off = 1; off < 1024; off <<= 1) {
        int v = (t >= off) ? ps[t - off] : 0;
        __syncthreads();
        ps[t] += v;
        __syncthreads();
    }
    int excl = (t > 0) ? ps[t - 1] : 0;
    g_start[2 * t] = excl;          g_cursor[2 * t] = excl;
    g_start[2 * t + 1] = excl + c0; g_cursor[2 * t + 1] = excl + c0;
    if (t == 1023) g_start[2048] = ps[1023];
}
__global__ void scatter_k(const int* __restrict__ ix) {
    int e = threadIdx.x + blockIdx.x * blockDim.x;
    if (e >= E_) return;
    int idx = atomicAdd(&g_cursor[ix[e]], 1);
    g_order[idx] = e;
}

// ---------------- fp16 GEMM, CTA 64x256, 256 threads, 2 CTAs/SM --------------------------
// MODE 0: C fp32 = A@W^T + bias
// MODE 1: C fp16 (EV); cols < 512 get exp() (logits), rest plain (vals)
#define PITCH 80
#define ABUF  5120             // 64 rows * 80
#define BUFSZ 25600            // A(64) + B(256) per stage
#define NSTAGE 4
#define SMEM_GEMM (NSTAGE * BUFSZ)  // 102400 per CTA; 2 CTAs -> 204800 < 227KB

template<int MODE>
__global__ __launch_bounds__(256, 2)
void gemm16(const __half* __restrict__ A, const __half* __restrict__ Bw,
            const float* __restrict__ bias, void* __restrict__ Cout, int ldc) {
    extern __shared__ char smem[];
    const uint32_t sb = smem_u32(smem);
    const int tid = threadIdx.x, lane = tid & 31, wid = tid >> 5;
    const int wm = wid >> 2, wn = wid & 3;            // 2x4 warps, warp tile 32x64
    const int m0 = blockIdx.y * 64, n0 = blockIdx.x * 256;

    float acc[2][8][4];
#pragma unroll
    for (int mt = 0; mt < 2; mt++)
#pragma unroll
        for (int nt = 0; nt < 8; nt++)
#pragma unroll
            for (int q = 0; q < 4; q++) acc[mt][nt][q] = 0.0f;

    // 1280 16B chunks per stage, 5 per thread
    auto load_buf = [&](int kc, int buf) {
        const int k0 = kc * 32;
        const uint32_t bb = sb + buf * BUFSZ;
#pragma unroll
        for (int t = 0; t < 5; t++) {
            int q = tid + t * 256;
            const __half* src;
            uint32_t base;
            int qq;
            if (q < 256) { src = A;  base = 0;    qq = q; }
            else         { src = Bw; base = ABUF; qq = q - 256; }
            int row = qq >> 2, c = qq & 3;
            int grow = (q < 256) ? (m0 + row) : (n0 + row);
            cp16(bb + base + (uint32_t)(row * PITCH + c * 16),
                 src + (size_t)grow * 512 + k0 + c * 8);
        }
    };

    load_buf(0, 0); CP_COMMIT();
    load_buf(1, 1); CP_COMMIT();
    load_buf(2, 2); CP_COMMIT();

    const uint32_t a_lane = (uint32_t)((wm * 32 + (lane & 15)) * PITCH + (lane >> 4) * 16);
    const uint32_t b_lane = (uint32_t)((wn * 64 + ((lane >> 4) & 1) * 8 + (lane & 7)) * PITCH +
                                       ((lane >> 3) & 1) * 16);

    for (int kc = 0; kc < 16; kc++) {
        CP_WAIT(2);
        __syncthreads();
        if (kc + 3 < 16) load_buf(kc + 3, (kc + 3) & (NSTAGE - 1));
        CP_COMMIT();

        const uint32_t bb = sb + (kc & (NSTAGE - 1)) * BUFSZ;
#pragma unroll
        for (int ks = 0; ks < 2; ks++) {
            uint32_t ah[2][4], bfr[4][4];
            uint32_t aoff = a_lane + (uint32_t)(ks * 32);
            ldsm4(ah[0], bb + aoff);
            ldsm4(ah[1], bb + aoff + 16 * PITCH);
#pragma unroll
            for (int np = 0; np < 4; np++)
                ldsm4(bfr[np], bb + ABUF + b_lane +
                                  (uint32_t)(np * 16 * PITCH + ks * 32));
#pragma unroll
            for (int np = 0; np < 4; np++) {
                mma_f16(acc[0][2 * np],     ah[0], bfr[np]);
                mma_f16(acc[0][2 * np + 1], ah[0], bfr[np] + 2);
                mma_f16(acc[1][2 * np],     ah[1], bfr[np]);
                mma_f16(acc[1][2 * np + 1], ah[1], bfr[np] + 2);
            }
        }
    }

    // epilogue: bias + stores
#pragma unroll
    for (int mt = 0; mt < 2; mt++) {
        int r0 = m0 + wm * 32 + mt * 16 + (lane >> 2);
#pragma unroll
        for (int nt = 0; nt < 8; nt++) {
            int col = n0 + wn * 64 + nt * 8 + (lane & 3) * 2;
            float b0 = bias[col], b1 = bias[col + 1];
            float v0 = acc[mt][nt][0] + b0, v1 = acc[mt][nt][1] + b1;
            float v2 = acc[mt][nt][2] + b0, v3 = acc[mt][nt][3] + b1;
            if (MODE == 0) {
                float* C = (float*)Cout;
                *(float2*)&C[(size_t)r0 * ldc + col]       = make_float2(v0, v1);
                *(float2*)&C[(size_t)(r0 + 8) * ldc + col] = make_float2(v2, v3);
            } else {
                if (n0 < 512) { v0 = __expf(v0); v1 = __expf(v1); v2 = __expf(v2); v3 = __expf(v3); }
                __half* C = (__half*)Cout;
                *(__half2*)&C[(size_t)r0 * ldc + col]       = __floats2half2_rn(v0, v1);
                *(__half2*)&C[(size_t)(r0 + 8) * ldc + col] = __floats2half2_rn(v2, v3);
            }
        }
    }
}

// ---------------- per-group softmax-weighted reduction (fp16 EV input) --------------------
__global__ __launch_bounds__(128)
void segreduce_k() {
    int g = blockIdx.x, b = blockIdx.y;
    int t = threadIdx.x;                 // t covers d = 4t..4t+3
    int s = g_start[g], e_end = g_start[g + 1];

    float4 den = make_float4(0.f, 0.f, 0.f, 0.f);
    float4 num = make_float4(0.f, 0.f, 0.f, 0.f);

    for (int j = s; j < e_end; j++) {
        int e = g_order[j];
        const __half2* row = (const __half2*)(g_EV + ((size_t)b * E_ + e) * 1024);
        __half2 w01 = row[2 * t],       w23 = row[2 * t + 1];
        __half2 v01 = row[256 + 2 * t], v23 = row[256 + 2 * t + 1];
        float2 w0 = __half22float2(w01), w1 = __half22float2(w23);
        float2 x0 = __half22float2(v01), x1 = __half22float2(v23);
        den.x += w0.x; den.y += w0.y; den.z += w1.x; den.w += w1.y;
        num.x += w0.x * x0.x; num.y += w0.y * x0.y;
        num.z += w1.x * x1.x; num.w += w1.y * x1.y;
    }
    float y0 = (den.x > 0.f) ? num.x / den.x : 0.f;
    float y1 = (den.y > 0.f) ? num.y / den.y : 0.f;
    float y2 = (den.z > 0.f) ? num.z / den.z : 0.f;
    float y3 = (den.w > 0.f) ? num.w / den.w : 0.f;

    size_t o2 = ((size_t)b * G_ + g) * 256 + (size_t)t * 2;   // half2 index
    ((__half2*)g_y16)[o2]     = __floats2half2_rn(y0, y1);
    ((__half2*)g_y16)[o2 + 1] = __floats2half2_rn(y2, y3);
}

// ---------------- gather out[b,e,:] = of[b, ix[e], :] -------------------------------------
__global__ void gather_k(const int* __restrict__ ix, float4* __restrict__ out) {
    size_t i = (size_t)blockIdx.x * blockDim.x + threadIdx.x;
    const size_t n4 = (size_t)B_ * E_ * (D_ / 4);
    if (i >= n4) return;
    int    d4 = (int)(i & 127);
    size_t be = i >> 7;
    int    e  = (int)(be & (E_ - 1));
    int    b  = (int)(be >> 15);
    const float4* of4 = (const float4*)g_of;
    out[i] = of4[((size_t)b * G_ + ix[e]) * 128 + d4];
}

// ---------------- launcher -----------------------------------------------------------------
extern "C" void kernel_launch(void* const* d_in, const int* in_sizes, int n_in,
                              void* d_out, int out_size) {
    const float* x  = (const float*)d_in[0];
    const int*   ix = (const int*)d_in[1];
    const float* Wf = (const float*)d_in[2];
    const float* bf = (const float*)d_in[3];
    const float* Wg = (const float*)d_in[4];
    const float* bg = (const float*)d_in[5];
    const float* Wh = (const float*)d_in[6];
    const float* bh = (const float*)d_in[7];
    float* out = (float*)d_out;

    __half *x16, *wstk, *wh, *y16, *ev;
    cudaGetSymbolAddress((void**)&x16, g_x16);
    cudaGetSymbolAddress((void**)&wstk, g_wstk);
    cudaGetSymbolAddress((void**)&wh, g_wh);
    cudaGetSymbolAddress((void**)&y16, g_y16);
    cudaGetSymbolAddress((void**)&ev, g_EV);
    float *pbstk, *pOF;
    cudaGetSymbolAddress((void**)&pbstk, g_bstk);
    cudaGetSymbolAddress((void**)&pOF, g_of);

    cudaFuncSetAttribute(gemm16<0>, cudaFuncAttributeMaxDynamicSharedMemorySize, SMEM_GEMM);
    cudaFuncSetAttribute(gemm16<1>, cudaFuncAttributeMaxDynamicSharedMemorySize, SMEM_GEMM);

    const int T = 256;

    // launch 0: fused prep (x cvt + weight cvts + bias + histogram)
    prep_k<<<33665, T>>>(x, Wg, Wf, Wh, bg, bf, ix);
    // launches 1-2: CSR scan + scatter
    scan_k<<<1, 1024>>>();
    scatter_k<<<E_ / T, T>>>(ix);
    // launch 3: projections (stacked) -> EV fp16 (exp on logit half)
    {
        dim3 grid(4, (B_ * E_) / 64);
        gemm16<1><<<grid, 256, SMEM_GEMM>>>(x16, wstk, pbstk, ev, 1024);
    }
    // launch 4: per-group softmax-weighted reduce -> y16
    {
        dim3 grid(G_, B_);
        segreduce_k<<<grid, 128>>>();
    }
    // launch 5: of = y @ Wh^T + bh (fp32)
    {
        dim3 grid(2, (B_ * G_) / 64);
        gemm16<0><<<grid, 256, SMEM_GEMM>>>(y16, wh, bh, pOF, 512);
    }
    // launch 6: gather to edges
    {
        size_t n4 = (size_t)B_ * E_ * (D_ / 4);
        gather_k<<<(unsigned)((n4 + T - 1) / T), T>>>(ix, (float4*)out);
    }
}

// round 11
// speedup vs baseline: 1.1302x; 1.0786x over previous
#include <cuda_runtime.h>
#include <cuda_fp16.h>
#include <cstdint>
#include <math.h>

#define B_ 2
#define E_ 32768
#define D_ 512
#define G_ 2048

// ---------------- scratch ------------------------------------------------------------
// EV: [m, 0:512] = exp(logit) fp16, [m, 512:1024] = val fp16
__device__ __half g_EV[(size_t)B_ * E_ * 1024];
__device__ __half g_wstk[1024 * 512];               // [Wg; Wf] fp16
__device__ float  g_bstk[1024];
__device__ __half g_wh[D_ * D_];
__device__ __half g_y16[(size_t)B_ * G_ * D_];
__device__ float  g_of[(size_t)B_ * G_ * D_];
__device__ int    g_cnt[G_], g_start[G_ + 1], g_cursor[G_], g_order[E_];

// ---------------- PTX helpers ---------------------------------------------------------
__device__ __forceinline__ uint32_t smem_u32(const void* p) {
    uint32_t a;
    asm("{ .reg .u64 t; cvta.to.shared.u64 t, %1; cvt.u32.u64 %0, t; }" : "=r"(a) : "l"(p));
    return a;
}
__device__ __forceinline__ void cp16(uint32_t s, const void* g) {
    asm volatile("cp.async.cg.shared.global [%0], [%1], 16;" :: "r"(s), "l"(g));
}
#define CP_COMMIT() asm volatile("cp.async.commit_group;" ::: "memory")
#define CP_WAIT(n)  asm volatile("cp.async.wait_group %0;" :: "n"(n) : "memory")

__device__ __forceinline__ void ldsm4(uint32_t* r, uint32_t addr) {
    asm volatile("ldmatrix.sync.aligned.m8n8.x4.shared.b16 {%0,%1,%2,%3}, [%4];"
                 : "=r"(r[0]), "=r"(r[1]), "=r"(r[2]), "=r"(r[3]) : "r"(addr));
}
__device__ __forceinline__ void mma_f16(float* c, const uint32_t* a, const uint32_t* b) {
    asm volatile(
        "mma.sync.aligned.m16n8k16.row.col.f32.f16.f16.f32 "
        "{%0,%1,%2,%3}, {%4,%5,%6,%7}, {%8,%9}, {%0,%1,%2,%3};"
        : "+f"(c[0]), "+f"(c[1]), "+f"(c[2]), "+f"(c[3])
        : "r"(a[0]), "r"(a[1]), "r"(a[2]), "r"(a[3]), "r"(b[0]), "r"(b[1]));
}
__device__ __forceinline__ uint32_t h2u(__half2 h) { return *reinterpret_cast<uint32_t*>(&h); }
__device__ __forceinline__ void sts128(uint32_t a, uint32_t v0, uint32_t v1,
                                       uint32_t v2, uint32_t v3) {
    asm volatile("st.shared.v4.b32 [%0], {%1,%2,%3,%4};"
                 :: "r"(a), "r"(v0), "r"(v1), "r"(v2), "r"(v3));
}

// ---------------- prep: weight cvts + bias + histogram -----------------------------------
// blocks [0,768): Wg/Wf/Wh -> fp16; block 768: bias; blocks [769, 897): histogram
__global__ void prep_k(const float* __restrict__ Wg, const float* __restrict__ Wf,
                       const float* __restrict__ Wh,
                       const float* __restrict__ bg, const float* __restrict__ bf,
                       const int* __restrict__ ix) {
    int bid = blockIdx.x, t = threadIdx.x;
    if (bid < 768) {
        const float* src = (bid < 256) ? Wg : ((bid < 512) ? Wf : Wh);
        __half* dst = (bid < 256) ? g_wstk : ((bid < 512) ? (g_wstk + 512 * 512) : g_wh);
        int i = (bid & 255) * 256 + t;          // float4 index, 65536 per matrix
        float4 f = ((const float4*)src)[i];
        ((__half2*)dst)[2 * i]     = __floats2half2_rn(f.x, f.y);
        ((__half2*)dst)[2 * i + 1] = __floats2half2_rn(f.z, f.w);
    } else if (bid == 768) {
        for (int q = t; q < 1024; q += 256)
            g_bstk[q] = (q < 512) ? bg[q] : bf[q - 512];
    } else {
        int e = (bid - 769) * 256 + t;
        if (e < E_) atomicAdd(&g_cnt[ix[e]], 1);
    }
}

// ---------------- CSR scan + scatter ------------------------------------------------------
__global__ void scan_k() {   // 1 block, 1024 threads; self-zeros g_cnt for graph replay
    __shared__ int ps[1024];
    int t = threadIdx.x;
    int c0 = g_cnt[2 * t], c1 = g_cnt[2 * t + 1];
    g_cnt[2 * t] = 0; g_cnt[2 * t + 1] = 0;
    ps[t] = c0 + c1;
    __syncthreads();
#pragma unroll
    for (int off = 1; off < 1024; off <<= 1) {
        int v = (t >= off) ? ps[t - off] : 0;
        __syncthreads();
        ps[t] += v;
        __syncthreads();
    }
    int excl = (t > 0) ? ps[t - 1] : 0;
    g_start[2 * t] = excl;          g_cursor[2 * t] = excl;
    g_start[2 * t + 1] = excl + c0; g_cursor[2 * t + 1] = excl + c0;
    if (t == 1023) g_start[2048] = ps[1023];
}
__global__ void scatter_k(const int* __restrict__ ix) {
    int e = threadIdx.x + blockIdx.x * blockDim.x;
    if (e >= E_) return;
    int idx = atomicAdd(&g_cursor[ix[e]], 1);
    g_order[idx] = e;
}

// ---------------- GEMM1: fp32 A (x) converted in-loader, fp16 B ---------------------------
// CTA 64x256, 256 threads, 2 CTAs/SM. A: 2-stage smem (fp16 after cvt), B: 4-stage cp.async.
// Output: EV fp16; cols<512 get exp().
#define PITCH 80
#define A_STG 5120             // 64 rows * 80
#define B_STG 20480            // 256 rows * 80
#define SMEM_X (2 * A_STG + 4 * B_STG)   // 92160
#define B_OFF  (2 * A_STG)

__global__ __launch_bounds__(256, 2)
void gemm16_x(const float* __restrict__ Af, const __half* __restrict__ Bw,
              const float* __restrict__ bias, __half* __restrict__ Cout, int ldc) {
    extern __shared__ char smem[];
    const uint32_t sb = smem_u32(smem);
    const int tid = threadIdx.x, lane = tid & 31, wid = tid >> 5;
    const int wm = wid >> 2, wn = wid & 3;            // 2x4 warps, warp tile 32x64
    const int m0 = blockIdx.y * 64, n0 = blockIdx.x * 256;

    float acc[2][8][4];
#pragma unroll
    for (int mt = 0; mt < 2; mt++)
#pragma unroll
        for (int nt = 0; nt < 8; nt++)
#pragma unroll
            for (int q = 0; q < 4; q++) acc[mt][nt][q] = 0.0f;

    // A loader: each thread owns (row = tid>>2, c4pair = (tid&3)*2) -> 8 floats -> 16B halves
    const int a_row = tid >> 2, a_c4 = (tid & 3) * 2;
    const float* a_gp = Af + (size_t)(m0 + a_row) * 512 + a_c4 * 4;
    float4 rA0, rA1;
    auto ldgA = [&](int kc) {
        rA0 = *(const float4*)(a_gp + kc * 32);
        rA1 = *(const float4*)(a_gp + kc * 32 + 4);
    };
    auto stsA = [&](int buf) {
        uint32_t dst = sb + buf * A_STG + (uint32_t)(a_row * PITCH + a_c4 * 8);
        sts128(dst, h2u(__floats2half2_rn(rA0.x, rA0.y)), h2u(__floats2half2_rn(rA0.z, rA0.w)),
                    h2u(__floats2half2_rn(rA1.x, rA1.y)), h2u(__floats2half2_rn(rA1.z, rA1.w)));
    };
    // B loader: 1024 16B chunks per stage, 4 per thread
    auto cpB = [&](int kc, int buf) {
        const int k0 = kc * 32;
#pragma unroll
        for (int t = 0; t < 4; t++) {
            int q = tid + t * 256, row = q >> 2, c = q & 3;
            cp16(sb + B_OFF + buf * B_STG + (uint32_t)(row * PITCH + c * 16),
                 Bw + (size_t)(n0 + row) * 512 + k0 + c * 8);
        }
    };

    // prologue
    ldgA(0); stsA(0);
    ldgA(1);
    cpB(0, 0); CP_COMMIT();
    cpB(1, 1); CP_COMMIT();
    cpB(2, 2); CP_COMMIT();

    const uint32_t a_lane = (uint32_t)((wm * 32 + (lane & 15)) * PITCH + (lane >> 4) * 16);
    const uint32_t b_lane = (uint32_t)((wn * 64 + ((lane >> 4) & 1) * 8 + (lane & 7)) * PITCH +
                                       ((lane >> 3) & 1) * 16);

    for (int kc = 0; kc < 16; kc++) {
        CP_WAIT(2);
        __syncthreads();
        if (kc + 1 < 16) stsA((kc + 1) & 1);     // regs hold A(kc+1)
        if (kc + 2 < 16) ldgA(kc + 2);
        if (kc + 3 < 16) cpB(kc + 3, (kc + 3) & 3);
        CP_COMMIT();

        const uint32_t ab = sb + (kc & 1) * A_STG;
        const uint32_t bb = sb + B_OFF + (kc & 3) * B_STG;
#pragma unroll
        for (int ks = 0; ks < 2; ks++) {
            uint32_t ah[2][4], bfr[4][4];
            uint32_t aoff = a_lane + (uint32_t)(ks * 32);
            ldsm4(ah[0], ab + aoff);
            ldsm4(ah[1], ab + aoff + 16 * PITCH);
#pragma unroll
            for (int np = 0; np < 4; np++)
                ldsm4(bfr[np], bb + b_lane + (uint32_t)(np * 16 * PITCH + ks * 32));
#pragma unroll
            for (int np = 0; np < 4; np++) {
                mma_f16(acc[0][2 * np],     ah[0], bfr[np]);
                mma_f16(acc[0][2 * np + 1], ah[0], bfr[np] + 2);
                mma_f16(acc[1][2 * np],     ah[1], bfr[np]);
                mma_f16(acc[1][2 * np + 1], ah[1], bfr[np] + 2);
            }
        }
    }

    // epilogue: bias (+ exp on logit half), fp16 stores
#pragma unroll
    for (int mt = 0; mt < 2; mt++) {
        int r0 = m0 + wm * 32 + mt * 16 + (lane >> 2);
#pragma unroll
        for (int nt = 0; nt < 8; nt++) {
            int col = n0 + wn * 64 + nt * 8 + (lane & 3) * 2;
            float b0 = bias[col], b1 = bias[col + 1];
            float v0 = acc[mt][nt][0] + b0, v1 = acc[mt][nt][1] + b1;
            float v2 = acc[mt][nt][2] + b0, v3 = acc[mt][nt][3] + b1;
            if (n0 < 512) { v0 = __expf(v0); v1 = __expf(v1); v2 = __expf(v2); v3 = __expf(v3); }
            *(__half2*)&Cout[(size_t)r0 * ldc + col]       = __floats2half2_rn(v0, v1);
            *(__half2*)&Cout[(size_t)(r0 + 8) * ldc + col] = __floats2half2_rn(v2, v3);
        }
    }
}

// ---------------- GEMM2: fp16 A (y16), fp32 out (unchanged path) --------------------------
#define BUFSZ0 25600           // A(64)+B(256) per stage
#define NSTAGE0 4
#define SMEM_Y (NSTAGE0 * BUFSZ0)  // 102400

__global__ __launch_bounds__(256, 2)
void gemm16_y(const __half* __restrict__ A, const __half* __restrict__ Bw,
              const float* __restrict__ bias, float* __restrict__ Cout, int ldc) {
    extern __shared__ char smem[];
    const uint32_t sb = smem_u32(smem);
    const int tid = threadIdx.x, lane = tid & 31, wid = tid >> 5;
    const int wm = wid >> 2, wn = wid & 3;
    const int m0 = blockIdx.y * 64, n0 = blockIdx.x * 256;

    float acc[2][8][4];
#pragma unroll
    for (int mt = 0; mt < 2; mt++)
#pragma unroll
        for (int nt = 0; nt < 8; nt++)
#pragma unroll
            for (int q = 0; q < 4; q++) acc[mt][nt][q] = 0.0f;

    auto load_buf = [&](int kc, int buf) {
        const int k0 = kc * 32;
        const uint32_t bb = sb + buf * BUFSZ0;
#pragma unroll
        for (int t = 0; t < 5; t++) {
            int q = tid + t * 256;
            const __half* src;
            uint32_t base;
            int qq;
            if (q < 256) { src = A;  base = 0;     qq = q; }
            else         { src = Bw; base = A_STG; qq = q - 256; }
            int row = qq >> 2, c = qq & 3;
            int grow = (q < 256) ? (m0 + row) : (n0 + row);
            cp16(bb + base + (uint32_t)(row * PITCH + c * 16),
                 src + (size_t)grow * 512 + k0 + c * 8);
        }
    };

    load_buf(0, 0); CP_COMMIT();
    load_buf(1, 1); CP_COMMIT();
    load_buf(2, 2); CP_COMMIT();

    const uint32_t a_lane = (uint32_t)((wm * 32 + (lane & 15)) * PITCH + (lane >> 4) * 16);
    const uint32_t b_lane = (uint32_t)((wn * 64 + ((lane >> 4) & 1) * 8 + (lane & 7)) * PITCH +
                                       ((lane >> 3) & 1) * 16);

    for (int kc = 0; kc < 16; kc++) {
        CP_WAIT(2);
        __syncthreads();
        if (kc + 3 < 16) load_buf(kc + 3, (kc + 3) & 3);
        CP_COMMIT();

        const uint32_t bb = sb + (kc & 3) * BUFSZ0;
#pragma unroll
        for (int ks = 0; ks < 2; ks++) {
            uint32_t ah[2][4], bfr[4][4];
            uint32_t aoff = a_lane + (uint32_t)(ks * 32);
            ldsm4(ah[0], bb + aoff);
            ldsm4(ah[1], bb + aoff + 16 * PITCH);
#pragma unroll
            for (int np = 0; np < 4; np++)
                ldsm4(bfr[np], bb + A_STG + b_lane +
                                  (uint32_t)(np * 16 * PITCH + ks * 32));
#pragma unroll
            for (int np = 0; np < 4; np++) {
                mma_f16(acc[0][2 * np],     ah[0], bfr[np]);
                mma_f16(acc[0][2 * np + 1], ah[0], bfr[np] + 2);
                mma_f16(acc[1][2 * np],     ah[1], bfr[np]);
                mma_f16(acc[1][2 * np + 1], ah[1], bfr[np] + 2);
            }
        }
    }

#pragma unroll
    for (int mt = 0; mt < 2; mt++) {
        int r0 = m0 + wm * 32 + mt * 16 + (lane >> 2);
#pragma unroll
        for (int nt = 0; nt < 8; nt++) {
            int col = n0 + wn * 64 + nt * 8 + (lane & 3) * 2;
            float b0 = bias[col], b1 = bias[col + 1];
            *(float2*)&Cout[(size_t)r0 * ldc + col] =
                make_float2(acc[mt][nt][0] + b0, acc[mt][nt][1] + b1);
            *(float2*)&Cout[(size_t)(r0 + 8) * ldc + col] =
                make_float2(acc[mt][nt][2] + b0, acc[mt][nt][3] + b1);
        }
    }
}

// ---------------- per-group softmax-weighted reduction (fp16 EV input) --------------------
__global__ __launch_bounds__(128)
void segreduce_k() {
    int g = blockIdx.x, b = blockIdx.y;
    int t = threadIdx.x;                 // t covers d = 4t..4t+3
    int s = g_start[g], e_end = g_start[g + 1];

    float4 den = make_float4(0.f, 0.f, 0.f, 0.f);
    float4 num = make_float4(0.f, 0.f, 0.f, 0.f);

    for (int j = s; j < e_end; j++) {
        int e = g_order[j];
        const __half2* row = (const __half2*)(g_EV + ((size_t)b * E_ + e) * 1024);
        __half2 w01 = row[2 * t],       w23 = row[2 * t + 1];
        __half2 v01 = row[256 + 2 * t], v23 = row[256 + 2 * t + 1];
        float2 w0 = __half22float2(w01), w1 = __half22float2(w23);
        float2 x0 = __half22float2(v01), x1 = __half22float2(v23);
        den.x += w0.x; den.y += w0.y; den.z += w1.x; den.w += w1.y;
        num.x += w0.x * x0.x; num.y += w0.y * x0.y;
        num.z += w1.x * x1.x; num.w += w1.y * x1.y;
    }
    float y0 = (den.x > 0.f) ? num.x / den.x : 0.f;
    float y1 = (den.y > 0.f) ? num.y / den.y : 0.f;
    float y2 = (den.z > 0.f) ? num.z / den.z : 0.f;
    float y3 = (den.w > 0.f) ? num.w / den.w : 0.f;

    size_t o2 = ((size_t)b * G_ + g) * 256 + (size_t)t * 2;   // half2 index
    ((__half2*)g_y16)[o2]     = __floats2half2_rn(y0, y1);
    ((__half2*)g_y16)[o2 + 1] = __floats2half2_rn(y2, y3);
}

// ---------------- gather out[b,e,:] = of[b, ix[e], :] -------------------------------------
__global__ void gather_k(const int* __restrict__ ix, float4* __restrict__ out) {
    size_t i = (size_t)blockIdx.x * blockDim.x + threadIdx.x;
    const size_t n4 = (size_t)B_ * E_ * (D_ / 4);
    if (i >= n4) return;
    int    d4 = (int)(i & 127);
    size_t be = i >> 7;
    int    e  = (int)(be & (E_ - 1));
    int    b  = (int)(be >> 15);
    const float4* of4 = (const float4*)g_of;
    out[i] = of4[((size_t)b * G_ + ix[e]) * 128 + d4];
}

// ---------------- launcher -----------------------------------------------------------------
extern "C" void kernel_launch(void* const* d_in, const int* in_sizes, int n_in,
                              void* d_out, int out_size) {
    const float* x  = (const float*)d_in[0];
    const int*   ix = (const int*)d_in[1];
    const float* Wf = (const float*)d_in[2];
    const float* bf = (const float*)d_in[3];
    const float* Wg = (const float*)d_in[4];
    const float* bg = (const float*)d_in[5];
    const float* Wh = (const float*)d_in[6];
    const float* bh = (const float*)d_in[7];
    float* out = (float*)d_out;

    __half *wstk, *wh, *y16, *ev;
    cudaGetSymbolAddress((void**)&wstk, g_wstk);
    cudaGetSymbolAddress((void**)&wh, g_wh);
    cudaGetSymbolAddress((void**)&y16, g_y16);
    cudaGetSymbolAddress((void**)&ev, g_EV);
    float *pbstk, *pOF;
    cudaGetSymbolAddress((void**)&pbstk, g_bstk);
    cudaGetSymbolAddress((void**)&pOF, g_of);

    cudaFuncSetAttribute(gemm16_x, cudaFuncAttributeMaxDynamicSharedMemorySize, SMEM_X);
    cudaFuncSetAttribute(gemm16_y, cudaFuncAttributeMaxDynamicSharedMemorySize, SMEM_Y);

    const int T = 256;

    // launch 0: prep (weight cvts + bias + histogram)
    prep_k<<<897, T>>>(Wg, Wf, Wh, bg, bf, ix);
    // launches 1-2: CSR scan + scatter
    scan_k<<<1, 1024>>>();
    scatter_k<<<E_ / T, T>>>(ix);
    // launch 3: projections (stacked) from fp32 x directly -> EV fp16
    {
        dim3 grid(4, (B_ * E_) / 64);
        gemm16_x<<<grid, 256, SMEM_X>>>(x, wstk, pbstk, ev, 1024);
    }
    // launch 4: per-group softmax-weighted reduce -> y16
    {
        dim3 grid(G_, B_);
        segreduce_k<<<grid, 128>>>();
    }
    // launch 5: of = y @ Wh^T + bh (fp32)
    {
        dim3 grid(2, (B_ * G_) / 64);
        gemm16_y<<<grid, 256, SMEM_Y>>>(y16, wh, bh, pOF, 512);
    }
    // launch 6: gather to edges
    {
        size_t n4 = (size_t)B_ * E_ * (D_ / 4);
        gather_k<<<(unsigned)((n4 + T - 1) / T), T>>>(ix, (float4*)out);
    }
}

// round 12
// speedup vs baseline: 1.1434x; 1.0116x over previous
#include <cuda_runtime.h>
#include <cuda_fp16.h>
#include <cstdint>
#include <math.h>

#define B_ 2
#define E_ 32768
#define D_ 512
#define G_ 2048

// ---------------- scratch ------------------------------------------------------------
// EV: [m, 0:512] = exp(logit) fp16, [m, 512:1024] = val fp16
__device__ __half g_EV[(size_t)B_ * E_ * 1024];
__device__ __half g_wstk[1024 * 512];               // [Wg; Wf] fp16
__device__ float  g_bstk[1024];
__device__ __half g_wh[D_ * D_];
__device__ __half g_y16[(size_t)B_ * G_ * D_];
__device__ int    g_cnt[G_], g_start[G_ + 1], g_cursor[G_], g_order[E_];

// ---------------- PTX helpers ---------------------------------------------------------
__device__ __forceinline__ uint32_t smem_u32(const void* p) {
    uint32_t a;
    asm("{ .reg .u64 t; cvta.to.shared.u64 t, %1; cvt.u32.u64 %0, t; }" : "=r"(a) : "l"(p));
    return a;
}
__device__ __forceinline__ void cp16(uint32_t s, const void* g) {
    asm volatile("cp.async.cg.shared.global [%0], [%1], 16;" :: "r"(s), "l"(g));
}
#define CP_COMMIT() asm volatile("cp.async.commit_group;" ::: "memory")
#define CP_WAIT(n)  asm volatile("cp.async.wait_group %0;" :: "n"(n) : "memory")

__device__ __forceinline__ void ldsm4(uint32_t* r, uint32_t addr) {
    asm volatile("ldmatrix.sync.aligned.m8n8.x4.shared.b16 {%0,%1,%2,%3}, [%4];"
                 : "=r"(r[0]), "=r"(r[1]), "=r"(r[2]), "=r"(r[3]) : "r"(addr));
}
__device__ __forceinline__ void mma_f16(float* c, const uint32_t* a, const uint32_t* b) {
    asm volatile(
        "mma.sync.aligned.m16n8k16.row.col.f32.f16.f16.f32 "
        "{%0,%1,%2,%3}, {%4,%5,%6,%7}, {%8,%9}, {%0,%1,%2,%3};"
        : "+f"(c[0]), "+f"(c[1]), "+f"(c[2]), "+f"(c[3])
        : "r"(a[0]), "r"(a[1]), "r"(a[2]), "r"(a[3]), "r"(b[0]), "r"(b[1]));
}
__device__ __forceinline__ uint32_t h2u(__half2 h) { return *reinterpret_cast<uint32_t*>(&h); }
__device__ __forceinline__ void sts128(uint32_t a, uint32_t v0, uint32_t v1,
                                       uint32_t v2, uint32_t v3) {
    asm volatile("st.shared.v4.b32 [%0], {%1,%2,%3,%4};"
                 :: "r"(a), "r"(v0), "r"(v1), "r"(v2), "r"(v3));
}

// ---------------- prep: weight cvts + bias + histogram -----------------------------------
__global__ void prep_k(const float* __restrict__ Wg, const float* __restrict__ Wf,
                       const float* __restrict__ Wh,
                       const float* __restrict__ bg, const float* __restrict__ bf,
                       const int* __restrict__ ix) {
    int bid = blockIdx.x, t = threadIdx.x;
    if (bid < 768) {
        const float* src = (bid < 256) ? Wg : ((bid < 512) ? Wf : Wh);
        __half* dst = (bid < 256) ? g_wstk : ((bid < 512) ? (g_wstk + 512 * 512) : g_wh);
        int i = (bid & 255) * 256 + t;          // float4 index, 65536 per matrix
        float4 f = ((const float4*)src)[i];
        ((__half2*)dst)[2 * i]     = __floats2half2_rn(f.x, f.y);
        ((__half2*)dst)[2 * i + 1] = __floats2half2_rn(f.z, f.w);
    } else if (bid == 768) {
        for (int q = t; q < 1024; q += 256)
            g_bstk[q] = (q < 512) ? bg[q] : bf[q - 512];
    } else {
        int e = (bid - 769) * 256 + t;
        if (e < E_) atomicAdd(&g_cnt[ix[e]], 1);
    }
}

// ---------------- CSR scan + scatter ------------------------------------------------------
__global__ void scan_k() {   // 1 block, 1024 threads; self-zeros g_cnt for graph replay
    __shared__ int ps[1024];
    int t = threadIdx.x;
    int c0 = g_cnt[2 * t], c1 = g_cnt[2 * t + 1];
    g_cnt[2 * t] = 0; g_cnt[2 * t + 1] = 0;
    ps[t] = c0 + c1;
    __syncthreads();
#pragma unroll
    for (int off = 1; off < 1024; off <<= 1) {
        int v = (t >= off) ? ps[t - off] : 0;
        __syncthreads();
        ps[t] += v;
        __syncthreads();
    }
    int excl = (t > 0) ? ps[t - 1] : 0;
    g_start[2 * t] = excl;          g_cursor[2 * t] = excl;
    g_start[2 * t + 1] = excl + c0; g_cursor[2 * t + 1] = excl + c0;
    if (t == 1023) g_start[2048] = ps[1023];
}
__global__ void scatter_k(const int* __restrict__ ix) {
    int e = threadIdx.x + blockIdx.x * blockDim.x;
    if (e >= E_) return;
    int idx = atomicAdd(&g_cursor[ix[e]], 1);
    g_order[idx] = e;
}

// ---------------- GEMM1: fp32 A converted in-loader, CTA 128x256, 512 threads -------------
#define PITCH 80
#define A_STG 10240            // 128 rows * 80
#define B_STG 20480            // 256 rows * 80
#define SMEM_X (2 * A_STG + 4 * B_STG)   // 102400
#define B_OFF  (2 * A_STG)

__global__ __launch_bounds__(512, 1)
void gemm16_x(const float* __restrict__ Af, const __half* __restrict__ Bw,
              const float* __restrict__ bias, __half* __restrict__ Cout, int ldc) {
    extern __shared__ char smem[];
    const uint32_t sb = smem_u32(smem);
    const int tid = threadIdx.x, lane = tid & 31, wid = tid >> 5;
    const int wm = wid >> 2, wn = wid & 3;            // 4x4 warps, warp tile 32x64
    const int m0 = blockIdx.y * 128, n0 = blockIdx.x * 256;

    float acc[2][8][4];
#pragma unroll
    for (int mt = 0; mt < 2; mt++)
#pragma unroll
        for (int nt = 0; nt < 8; nt++)
#pragma unroll
            for (int q = 0; q < 4; q++) acc[mt][nt][q] = 0.0f;

    // A loader: thread owns (row = tid>>2, c4pair = (tid&3)*2) -> 8 fp32 -> 16B fp16
    const int a_row = tid >> 2, a_c4 = (tid & 3) * 2;
    const float* a_gp = Af + (size_t)(m0 + a_row) * 512 + a_c4 * 4;
    float4 rA0, rA1;
    auto ldgA = [&](int kc) {
        rA0 = *(const float4*)(a_gp + kc * 32);
        rA1 = *(const float4*)(a_gp + kc * 32 + 4);
    };
    auto stsA = [&](int buf) {
        uint32_t dst = sb + buf * A_STG + (uint32_t)(a_row * PITCH + a_c4 * 8);
        sts128(dst, h2u(__floats2half2_rn(rA0.x, rA0.y)), h2u(__floats2half2_rn(rA0.z, rA0.w)),
                    h2u(__floats2half2_rn(rA1.x, rA1.y)), h2u(__floats2half2_rn(rA1.z, rA1.w)));
    };
    // B loader: 1024 16B chunks per stage, 2 per thread
    auto cpB = [&](int kc, int buf) {
        const int k0 = kc * 32;
#pragma unroll
        for (int t = 0; t < 2; t++) {
            int q = tid + t * 512, row = q >> 2, c = q & 3;
            cp16(sb + B_OFF + buf * B_STG + (uint32_t)(row * PITCH + c * 16),
                 Bw + (size_t)(n0 + row) * 512 + k0 + c * 8);
        }
    };

    ldgA(0); stsA(0);
    ldgA(1);
    cpB(0, 0); CP_COMMIT();
    cpB(1, 1); CP_COMMIT();
    cpB(2, 2); CP_COMMIT();

    const uint32_t a_lane = (uint32_t)((wm * 32 + (lane & 15)) * PITCH + (lane >> 4) * 16);
    const uint32_t b_lane = (uint32_t)((wn * 64 + ((lane >> 4) & 1) * 8 + (lane & 7)) * PITCH +
                                       ((lane >> 3) & 1) * 16);

    for (int kc = 0; kc < 16; kc++) {
        CP_WAIT(2);
        __syncthreads();
        if (kc + 1 < 16) stsA((kc + 1) & 1);
        if (kc + 2 < 16) ldgA(kc + 2);
        if (kc + 3 < 16) cpB(kc + 3, (kc + 3) & 3);
        CP_COMMIT();

        const uint32_t ab = sb + (kc & 1) * A_STG;
        const uint32_t bb = sb + B_OFF + (kc & 3) * B_STG;
#pragma unroll
        for (int ks = 0; ks < 2; ks++) {
            uint32_t ah[2][4], bfr[4][4];
            uint32_t aoff = a_lane + (uint32_t)(ks * 32);
            ldsm4(ah[0], ab + aoff);
            ldsm4(ah[1], ab + aoff + 16 * PITCH);
#pragma unroll
            for (int np = 0; np < 4; np++)
                ldsm4(bfr[np], bb + b_lane + (uint32_t)(np * 16 * PITCH + ks * 32));
#pragma unroll
            for (int np = 0; np < 4; np++) {
                mma_f16(acc[0][2 * np],     ah[0], bfr[np]);
                mma_f16(acc[0][2 * np + 1], ah[0], bfr[np] + 2);
                mma_f16(acc[1][2 * np],     ah[1], bfr[np]);
                mma_f16(acc[1][2 * np + 1], ah[1], bfr[np] + 2);
            }
        }
    }

    // epilogue: bias (+ exp on logit half), fp16 stores
#pragma unroll
    for (int mt = 0; mt < 2; mt++) {
        int r0 = m0 + wm * 32 + mt * 16 + (lane >> 2);
#pragma unroll
        for (int nt = 0; nt < 8; nt++) {
            int col = n0 + wn * 64 + nt * 8 + (lane & 3) * 2;
            float b0 = bias[col], b1 = bias[col + 1];
            float v0 = acc[mt][nt][0] + b0, v1 = acc[mt][nt][1] + b1;
            float v2 = acc[mt][nt][2] + b0, v3 = acc[mt][nt][3] + b1;
            if (n0 < 512) { v0 = __expf(v0); v1 = __expf(v1); v2 = __expf(v2); v3 = __expf(v3); }
            *(__half2*)&Cout[(size_t)r0 * ldc + col]       = __floats2half2_rn(v0, v1);
            *(__half2*)&Cout[(size_t)(r0 + 8) * ldc + col] = __floats2half2_rn(v2, v3);
        }
    }
}

// ---------------- GEMM2 + fused output scatter --------------------------------------------
// CTA 64x256, 256 threads, 2/SM. After mainloop: stage tile in smem, then warp-cooperative
// scatter of each (b,g) row slice to out[b,e, n0:n0+256] for all edges e of group g.
#define BUFSZ0 25600           // A(64*80) + B(256*80) per stage
#define SMEM_Y (4 * BUFSZ0)    // 102400 ; stage uses first 64*264*4 = 67584 (buffers 0-2)
#define SPITCH 264

__global__ __launch_bounds__(256, 2)
void gemm16_y(const __half* __restrict__ A, const __half* __restrict__ Bw,
              const float* __restrict__ bias, float* __restrict__ out) {
    extern __shared__ char smem[];
    const uint32_t sb = smem_u32(smem);
    const int tid = threadIdx.x, lane = tid & 31, wid = tid >> 5;
    const int wm = wid >> 2, wn = wid & 3;
    const int m0 = blockIdx.y * 64, n0 = blockIdx.x * 256;

    float acc[2][8][4];
#pragma unroll
    for (int mt = 0; mt < 2; mt++)
#pragma unroll
        for (int nt = 0; nt < 8; nt++)
#pragma unroll
            for (int q = 0; q < 4; q++) acc[mt][nt][q] = 0.0f;

    auto load_buf = [&](int kc, int buf) {
        const int k0 = kc * 32;
        const uint32_t bb = sb + buf * BUFSZ0;
#pragma unroll
        for (int t = 0; t < 5; t++) {
            int q = tid + t * 256;
            const __half* src;
            uint32_t base;
            int qq;
            if (q < 256) { src = A;  base = 0;       qq = q; }
            else         { src = Bw; base = 64 * 80; qq = q - 256; }
            int row = qq >> 2, c = qq & 3;
            int grow = (q < 256) ? (m0 + row) : (n0 + row);
            cp16(bb + base + (uint32_t)(row * PITCH + c * 16),
                 src + (size_t)grow * 512 + k0 + c * 8);
        }
    };

    load_buf(0, 0); CP_COMMIT();
    load_buf(1, 1); CP_COMMIT();
    load_buf(2, 2); CP_COMMIT();

    const uint32_t a_lane = (uint32_t)((wm * 32 + (lane & 15)) * PITCH + (lane >> 4) * 16);
    const uint32_t b_lane = (uint32_t)((wn * 64 + ((lane >> 4) & 1) * 8 + (lane & 7)) * PITCH +
                                       ((lane >> 3) & 1) * 16);

    for (int kc = 0; kc < 16; kc++) {
        CP_WAIT(2);
        __syncthreads();
        if (kc + 3 < 16) load_buf(kc + 3, (kc + 3) & 3);
        CP_COMMIT();

        const uint32_t bb = sb + (kc & 3) * BUFSZ0;
#pragma unroll
        for (int ks = 0; ks < 2; ks++) {
            uint32_t ah[2][4], bfr[4][4];
            uint32_t aoff = a_lane + (uint32_t)(ks * 32);
            ldsm4(ah[0], bb + aoff);
            ldsm4(ah[1], bb + aoff + 16 * PITCH);
#pragma unroll
            for (int np = 0; np < 4; np++)
                ldsm4(bfr[np], bb + 64 * 80 + b_lane +
                                  (uint32_t)(np * 16 * PITCH + ks * 32));
#pragma unroll
            for (int np = 0; np < 4; np++) {
                mma_f16(acc[0][2 * np],     ah[0], bfr[np]);
                mma_f16(acc[0][2 * np + 1], ah[0], bfr[np] + 2);
                mma_f16(acc[1][2 * np],     ah[1], bfr[np]);
                mma_f16(acc[1][2 * np + 1], ah[1], bfr[np] + 2);
            }
        }
    }

    // stage tile (bias added) in smem: 64 rows x 256 cols, pitch 264 floats
    float* stage = (float*)smem;
    __syncthreads();                 // all warps done with buffers 0-2 (last iter reads buf 3)
#pragma unroll
    for (int mt = 0; mt < 2; mt++) {
#pragma unroll
        for (int nt = 0; nt < 8; nt++) {
            int colL = wn * 64 + nt * 8 + (lane & 3) * 2;
            float b0 = bias[n0 + colL], b1 = bias[n0 + colL + 1];
            int rL0 = wm * 32 + mt * 16 + (lane >> 2);
            *(float2*)&stage[rL0 * SPITCH + colL] =
                make_float2(acc[mt][nt][0] + b0, acc[mt][nt][1] + b1);
            *(float2*)&stage[(rL0 + 8) * SPITCH + colL] =
                make_float2(acc[mt][nt][2] + b0, acc[mt][nt][3] + b1);
        }
    }
    __syncthreads();

    // warp-cooperative scatter: warp w handles rows w, w+8, ...; 512B coalesced lines
    for (int r = wid; r < 64; r += 8) {
        int rg = m0 + r;
        int g = rg & (G_ - 1), b = rg >> 11;
        int s = g_start[g], e_end = g_start[g + 1];
        float4 v0 = *(float4*)&stage[r * SPITCH + 4 * lane];
        float4 v1 = *(float4*)&stage[r * SPITCH + 128 + 4 * lane];
        for (int j = s; j < e_end; j++) {
            float* base = out + ((size_t)b * E_ + g_order[j]) * 512 + n0;
            *(float4*)(base + 4 * lane)       = v0;
            *(float4*)(base + 128 + 4 * lane) = v1;
        }
    }
}

// ---------------- per-group softmax-weighted reduction (fp16 EV input) --------------------
__global__ __launch_bounds__(128)
void segreduce_k() {
    int g = blockIdx.x, b = blockIdx.y;
    int t = threadIdx.x;                 // t covers d = 4t..4t+3
    int s = g_start[g], e_end = g_start[g + 1];

    float4 den = make_float4(0.f, 0.f, 0.f, 0.f);
    float4 num = make_float4(0.f, 0.f, 0.f, 0.f);

    for (int j = s; j < e_end; j++) {
        int e = g_order[j];
        const __half2* row = (const __half2*)(g_EV + ((size_t)b * E_ + e) * 1024);
        __half2 w01 = row[2 * t],       w23 = row[2 * t + 1];
        __half2 v01 = row[256 + 2 * t], v23 = row[256 + 2 * t + 1];
        float2 w0 = __half22float2(w01), w1 = __half22float2(w23);
        float2 x0 = __half22float2(v01), x1 = __half22float2(v23);
        den.x += w0.x; den.y += w0.y; den.z += w1.x; den.w += w1.y;
        num.x += w0.x * x0.x; num.y += w0.y * x0.y;
        num.z += w1.x * x1.x; num.w += w1.y * x1.y;
    }
    float y0 = (den.x > 0.f) ? num.x / den.x : 0.f;
    float y1 = (den.y > 0.f) ? num.y / den.y : 0.f;
    float y2 = (den.z > 0.f) ? num.z / den.z : 0.f;
    float y3 = (den.w > 0.f) ? num.w / den.w : 0.f;

    size_t o2 = ((size_t)b * G_ + g) * 256 + (size_t)t * 2;   // half2 index
    ((__half2*)g_y16)[o2]     = __floats2half2_rn(y0, y1);
    ((__half2*)g_y16)[o2 + 1] = __floats2half2_rn(y2, y3);
}

// ---------------- launcher -----------------------------------------------------------------
extern "C" void kernel_launch(void* const* d_in, const int* in_sizes, int n_in,
                              void* d_out, int out_size) {
    const float* x  = (const float*)d_in[0];
    const int*   ix = (const int*)d_in[1];
    const float* Wf = (const float*)d_in[2];
    const float* bf = (const float*)d_in[3];
    const float* Wg = (const float*)d_in[4];
    const float* bg = (const float*)d_in[5];
    const float* Wh = (const float*)d_in[6];
    const float* bh = (const float*)d_in[7];
    float* out = (float*)d_out;

    __half *wstk, *wh, *y16, *ev;
    cudaGetSymbolAddress((void**)&wstk, g_wstk);
    cudaGetSymbolAddress((void**)&wh, g_wh);
    cudaGetSymbolAddress((void**)&y16, g_y16);
    cudaGetSymbolAddress((void**)&ev, g_EV);
    float* pbstk;
    cudaGetSymbolAddress((void**)&pbstk, g_bstk);

    cudaFuncSetAttribute(gemm16_x, cudaFuncAttributeMaxDynamicSharedMemorySize, SMEM_X);
    cudaFuncSetAttribute(gemm16_y, cudaFuncAttributeMaxDynamicSharedMemorySize, SMEM_Y);

    const int T = 256;

    // launch 0: prep (weight cvts + bias + histogram)
    prep_k<<<897, T>>>(Wg, Wf, Wh, bg, bf, ix);
    // launches 1-2: CSR scan + scatter
    scan_k<<<1, 1024>>>();
    scatter_k<<<E_ / T, T>>>(ix);
    // launch 3: projections (stacked) from fp32 x directly -> EV fp16
    {
        dim3 grid(4, (B_ * E_) / 128);
        gemm16_x<<<grid, 512, SMEM_X>>>(x, wstk, pbstk, ev, 1024);
    }
    // launch 4: per-group softmax-weighted reduce -> y16
    {
        dim3 grid(G_, B_);
        segreduce_k<<<grid, 128>>>();
    }
    // launch 5: of = y @ Wh^T + bh, scattered straight to out[b,e,:]
    {
        dim3 grid(2, (B_ * G_) / 64);
        gemm16_y<<<grid, 256, SMEM_Y>>>(y16, wh, bh, out);
    }
}

// round 13
// speedup vs baseline: 1.1694x; 1.0227x over previous
#include <cuda_runtime.h>
#include <cuda_fp16.h>
#include <cstdint>
#include <math.h>

#define B_ 2
#define E_ 32768
#define D_ 512
#define G_ 2048

// ---------------- scratch ------------------------------------------------------------
// EV: [m, 0:512] = exp(logit) fp16, [m, 512:1024] = val fp16
__device__ __half g_EV[(size_t)B_ * E_ * 1024];
__device__ __half g_wstk[1024 * 512];               // [Wg; Wf] fp16
__device__ float  g_bstk[1024];
__device__ __half g_wh[D_ * D_];
__device__ __half g_y16[(size_t)B_ * G_ * D_];
__device__ int    g_cnt[G_], g_start[G_ + 1], g_cursor[G_], g_order[E_];

// ---------------- PTX helpers ---------------------------------------------------------
__device__ __forceinline__ uint32_t smem_u32(const void* p) {
    uint32_t a;
    asm("{ .reg .u64 t; cvta.to.shared.u64 t, %1; cvt.u32.u64 %0, t; }" : "=r"(a) : "l"(p));
    return a;
}
__device__ __forceinline__ void cp16(uint32_t s, const void* g) {
    asm volatile("cp.async.cg.shared.global [%0], [%1], 16;" :: "r"(s), "l"(g));
}
#define CP_COMMIT() asm volatile("cp.async.commit_group;" ::: "memory")
#define CP_WAIT(n)  asm volatile("cp.async.wait_group %0;" :: "n"(n) : "memory")

__device__ __forceinline__ void ldsm4(uint32_t* r, uint32_t addr) {
    asm volatile("ldmatrix.sync.aligned.m8n8.x4.shared.b16 {%0,%1,%2,%3}, [%4];"
                 : "=r"(r[0]), "=r"(r[1]), "=r"(r[2]), "=r"(r[3]) : "r"(addr));
}
__device__ __forceinline__ void mma_f16(float* c, const uint32_t* a, const uint32_t* b) {
    asm volatile(
        "mma.sync.aligned.m16n8k16.row.col.f32.f16.f16.f32 "
        "{%0,%1,%2,%3}, {%4,%5,%6,%7}, {%8,%9}, {%0,%1,%2,%3};"
        : "+f"(c[0]), "+f"(c[1]), "+f"(c[2]), "+f"(c[3])
        : "r"(a[0]), "r"(a[1]), "r"(a[2]), "r"(a[3]), "r"(b[0]), "r"(b[1]));
}
__device__ __forceinline__ uint32_t h2u(__half2 h) { return *reinterpret_cast<uint32_t*>(&h); }
__device__ __forceinline__ void sts128(uint32_t a, uint32_t v0, uint32_t v1,
                                       uint32_t v2, uint32_t v3) {
    asm volatile("st.shared.v4.b32 [%0], {%1,%2,%3,%4};"
                 :: "r"(a), "r"(v0), "r"(v1), "r"(v2), "r"(v3));
}

// ---------------- prep: weight cvts + bias + histogram -----------------------------------
__global__ void prep_k(const float* __restrict__ Wg, const float* __restrict__ Wf,
                       const float* __restrict__ Wh,
                       const float* __restrict__ bg, const float* __restrict__ bf,
                       const int* __restrict__ ix) {
    int bid = blockIdx.x, t = threadIdx.x;
    if (bid < 768) {
        const float* src = (bid < 256) ? Wg : ((bid < 512) ? Wf : Wh);
        __half* dst = (bid < 256) ? g_wstk : ((bid < 512) ? (g_wstk + 512 * 512) : g_wh);
        int i = (bid & 255) * 256 + t;          // float4 index, 65536 per matrix
        float4 f = ((const float4*)src)[i];
        ((__half2*)dst)[2 * i]     = __floats2half2_rn(f.x, f.y);
        ((__half2*)dst)[2 * i + 1] = __floats2half2_rn(f.z, f.w);
    } else if (bid == 768) {
        for (int q = t; q < 1024; q += 256)
            g_bstk[q] = (q < 512) ? bg[q] : bf[q - 512];
    } else {
        int e = (bid - 769) * 256 + t;
        if (e < E_) atomicAdd(&g_cnt[ix[e]], 1);
    }
}

// ---------------- CSR scan (warp-shuffle, 256 threads) + scatter ---------------------------
__global__ __launch_bounds__(256)
void scan_k() {           // self-zeros g_cnt for graph replay
    __shared__ int wsum[8];
    int t = threadIdx.x, lane = t & 31, wid = t >> 5;
    int4 c0 = *(int4*)&g_cnt[8 * t];
    int4 c1 = *(int4*)&g_cnt[8 * t + 4];
    *(int4*)&g_cnt[8 * t]     = make_int4(0, 0, 0, 0);
    *(int4*)&g_cnt[8 * t + 4] = make_int4(0, 0, 0, 0);
    int l[8] = {c0.x, c0.y, c0.z, c0.w, c1.x, c1.y, c1.z, c1.w};
    int lsum = 0;
#pragma unroll
    for (int i = 0; i < 8; i++) lsum += l[i];
    int v = lsum;
#pragma unroll
    for (int off = 1; off < 32; off <<= 1) {
        int n = __shfl_up_sync(0xFFFFFFFFu, v, off);
        if (lane >= off) v += n;
    }
    if (lane == 31) wsum[wid] = v;
    __syncthreads();
    if (t == 0) {
        int a = 0;
#pragma unroll
        for (int w = 0; w < 8; w++) { int x = wsum[w]; wsum[w] = a; a += x; }
    }
    __syncthreads();
    int run = wsum[wid] + (v - lsum);
#pragma unroll
    for (int i = 0; i < 8; i++) {
        g_start[8 * t + i]  = run;
        g_cursor[8 * t + i] = run;
        run += l[i];
    }
    if (t == 255) g_start[2048] = run;
}
__global__ void scatter_k(const int* __restrict__ ix) {
    int e = threadIdx.x + blockIdx.x * blockDim.x;
    if (e >= E_) return;
    int idx = atomicAdd(&g_cursor[ix[e]], 1);
    g_order[idx] = e;
}

// ---------------- GEMM1: fp32 A converted in-loader, CTA 128x256, 512 threads -------------
#define PITCH 80
#define A_STG 10240            // 128 rows * 80
#define B_STG 20480            // 256 rows * 80
#define SMEM_X (2 * A_STG + 4 * B_STG)   // 102400
#define B_OFF  (2 * A_STG)

__global__ __launch_bounds__(512, 1)
void gemm16_x(const float* __restrict__ Af, const __half* __restrict__ Bw,
              const float* __restrict__ bias, __half* __restrict__ Cout, int ldc) {
    extern __shared__ char smem[];
    const uint32_t sb = smem_u32(smem);
    const int tid = threadIdx.x, lane = tid & 31, wid = tid >> 5;
    const int wm = wid >> 2, wn = wid & 3;            // 4x4 warps, warp tile 32x64
    const int m0 = blockIdx.y * 128, n0 = blockIdx.x * 256;

    float acc[2][8][4];
#pragma unroll
    for (int mt = 0; mt < 2; mt++)
#pragma unroll
        for (int nt = 0; nt < 8; nt++)
#pragma unroll
            for (int q = 0; q < 4; q++) acc[mt][nt][q] = 0.0f;

    const int a_row = tid >> 2, a_c4 = (tid & 3) * 2;
    const float* a_gp = Af + (size_t)(m0 + a_row) * 512 + a_c4 * 4;
    float4 rA0, rA1;
    auto ldgA = [&](int kc) {
        rA0 = *(const float4*)(a_gp + kc * 32);
        rA1 = *(const float4*)(a_gp + kc * 32 + 4);
    };
    auto stsA = [&](int buf) {
        uint32_t dst = sb + buf * A_STG + (uint32_t)(a_row * PITCH + a_c4 * 8);
        sts128(dst, h2u(__floats2half2_rn(rA0.x, rA0.y)), h2u(__floats2half2_rn(rA0.z, rA0.w)),
                    h2u(__floats2half2_rn(rA1.x, rA1.y)), h2u(__floats2half2_rn(rA1.z, rA1.w)));
    };
    auto cpB = [&](int kc, int buf) {
        const int k0 = kc * 32;
#pragma unroll
        for (int t = 0; t < 2; t++) {
            int q = tid + t * 512, row = q >> 2, c = q & 3;
            cp16(sb + B_OFF + buf * B_STG + (uint32_t)(row * PITCH + c * 16),
                 Bw + (size_t)(n0 + row) * 512 + k0 + c * 8);
        }
    };

    ldgA(0); stsA(0);
    ldgA(1);
    cpB(0, 0); CP_COMMIT();
    cpB(1, 1); CP_COMMIT();
    cpB(2, 2); CP_COMMIT();

    const uint32_t a_lane = (uint32_t)((wm * 32 + (lane & 15)) * PITCH + (lane >> 4) * 16);
    const uint32_t b_lane = (uint32_t)((wn * 64 + ((lane >> 4) & 1) * 8 + (lane & 7)) * PITCH +
                                       ((lane >> 3) & 1) * 16);

    for (int kc = 0; kc < 16; kc++) {
        CP_WAIT(2);
        __syncthreads();
        if (kc + 1 < 16) stsA((kc + 1) & 1);
        if (kc + 2 < 16) ldgA(kc + 2);
        if (kc + 3 < 16) cpB(kc + 3, (kc + 3) & 3);
        CP_COMMIT();

        const uint32_t ab = sb + (kc & 1) * A_STG;
        const uint32_t bb = sb + B_OFF + (kc & 3) * B_STG;
#pragma unroll
        for (int ks = 0; ks < 2; ks++) {
            uint32_t ah[2][4], bfr[4][4];
            uint32_t aoff = a_lane + (uint32_t)(ks * 32);
            ldsm4(ah[0], ab + aoff);
            ldsm4(ah[1], ab + aoff + 16 * PITCH);
#pragma unroll
            for (int np = 0; np < 4; np++)
                ldsm4(bfr[np], bb + b_lane + (uint32_t)(np * 16 * PITCH + ks * 32));
#pragma unroll
            for (int np = 0; np < 4; np++) {
                mma_f16(acc[0][2 * np],     ah[0], bfr[np]);
                mma_f16(acc[0][2 * np + 1], ah[0], bfr[np] + 2);
                mma_f16(acc[1][2 * np],     ah[1], bfr[np]);
                mma_f16(acc[1][2 * np + 1], ah[1], bfr[np] + 2);
            }
        }
    }

#pragma unroll
    for (int mt = 0; mt < 2; mt++) {
        int r0 = m0 + wm * 32 + mt * 16 + (lane >> 2);
#pragma unroll
        for (int nt = 0; nt < 8; nt++) {
            int col = n0 + wn * 64 + nt * 8 + (lane & 3) * 2;
            float b0 = bias[col], b1 = bias[col + 1];
            float v0 = acc[mt][nt][0] + b0, v1 = acc[mt][nt][1] + b1;
            float v2 = acc[mt][nt][2] + b0, v3 = acc[mt][nt][3] + b1;
            if (n0 < 512) { v0 = __expf(v0); v1 = __expf(v1); v2 = __expf(v2); v3 = __expf(v3); }
            *(__half2*)&Cout[(size_t)r0 * ldc + col]       = __floats2half2_rn(v0, v1);
            *(__half2*)&Cout[(size_t)(r0 + 8) * ldc + col] = __floats2half2_rn(v2, v3);
        }
    }
}

// ---------------- GEMM2 + fused output scatter: CTA 64x128, 256 threads -------------------
// 8 warps = 2(m) x 4(n), warp tile 32x32. After mainloop: stage in smem, warp-coalesced
// scatter of each (b,g) row slice to out[b,e, n0:n0+128] for all edges of group g.
#define A_STG2 5120            // 64 * 80
#define B_STG2 10240           // 128 * 80
#define BUF2   15360
#define SMEM_Y (4 * BUF2)      // 61440; epilogue stage 64*132*4 = 33792 (buffers 0-1 region)
#define SPITCH 132

__global__ __launch_bounds__(256, 2)
void gemm16_y(const __half* __restrict__ A, const __half* __restrict__ Bw,
              const float* __restrict__ bias, float* __restrict__ out) {
    extern __shared__ char smem[];
    const uint32_t sb = smem_u32(smem);
    const int tid = threadIdx.x, lane = tid & 31, wid = tid >> 5;
    const int wm = wid >> 2, wn = wid & 3;
    const int m0 = blockIdx.y * 64, n0 = blockIdx.x * 128;

    float acc[2][4][4];
#pragma unroll
    for (int mt = 0; mt < 2; mt++)
#pragma unroll
        for (int nt = 0; nt < 4; nt++)
#pragma unroll
            for (int q = 0; q < 4; q++) acc[mt][nt][q] = 0.0f;

    auto load_buf = [&](int kc, int buf) {
        const int k0 = kc * 32;
        const uint32_t bb = sb + buf * BUF2;
#pragma unroll
        for (int t = 0; t < 3; t++) {
            int q = tid + t * 256;
            const __half* src;
            uint32_t base;
            int qq;
            if (q < 256) { src = A;  base = 0;      qq = q; }
            else         { src = Bw; base = A_STG2; qq = q - 256; }
            int row = qq >> 2, c = qq & 3;
            int grow = (q < 256) ? (m0 + row) : (n0 + row);
            cp16(bb + base + (uint32_t)(row * PITCH + c * 16),
                 src + (size_t)grow * 512 + k0 + c * 8);
        }
    };

    load_buf(0, 0); CP_COMMIT();
    load_buf(1, 1); CP_COMMIT();
    load_buf(2, 2); CP_COMMIT();

    const uint32_t a_lane = (uint32_t)((wm * 32 + (lane & 15)) * PITCH + (lane >> 4) * 16);
    const uint32_t b_lane = (uint32_t)((wn * 32 + ((lane >> 4) & 1) * 8 + (lane & 7)) * PITCH +
                                       ((lane >> 3) & 1) * 16);

    for (int kc = 0; kc < 16; kc++) {
        CP_WAIT(2);
        __syncthreads();
        if (kc + 3 < 16) load_buf(kc + 3, (kc + 3) & 3);
        CP_COMMIT();

        const uint32_t bb = sb + (kc & 3) * BUF2;
#pragma unroll
        for (int ks = 0; ks < 2; ks++) {
            uint32_t ah[2][4], bfr[2][4];
            uint32_t aoff = a_lane + (uint32_t)(ks * 32);
            ldsm4(ah[0], bb + aoff);
            ldsm4(ah[1], bb + aoff + 16 * PITCH);
#pragma unroll
            for (int np = 0; np < 2; np++)
                ldsm4(bfr[np], bb + A_STG2 + b_lane +
                                  (uint32_t)(np * 16 * PITCH + ks * 32));
#pragma unroll
            for (int np = 0; np < 2; np++) {
                mma_f16(acc[0][2 * np],     ah[0], bfr[np]);
                mma_f16(acc[0][2 * np + 1], ah[0], bfr[np] + 2);
                mma_f16(acc[1][2 * np],     ah[1], bfr[np]);
                mma_f16(acc[1][2 * np + 1], ah[1], bfr[np] + 2);
            }
        }
    }

    // stage tile (bias added) in smem: 64 rows x 128 cols, pitch 132 floats
    float* stage = (float*)smem;
    __syncthreads();
#pragma unroll
    for (int mt = 0; mt < 2; mt++) {
#pragma unroll
        for (int nt = 0; nt < 4; nt++) {
            int colL = wn * 32 + nt * 8 + (lane & 3) * 2;
            float b0 = bias[n0 + colL], b1 = bias[n0 + colL + 1];
            int rL0 = wm * 32 + mt * 16 + (lane >> 2);
            *(float2*)&stage[rL0 * SPITCH + colL] =
                make_float2(acc[mt][nt][0] + b0, acc[mt][nt][1] + b1);
            *(float2*)&stage[(rL0 + 8) * SPITCH + colL] =
                make_float2(acc[mt][nt][2] + b0, acc[mt][nt][3] + b1);
        }
    }
    __syncthreads();

    // warp-cooperative scatter: warp w handles rows w, w+8, ...; 512B coalesced lines
    for (int r = wid; r < 64; r += 8) {
        int rg = m0 + r;
        int g = rg & (G_ - 1), b = rg >> 11;
        int s = g_start[g], e_end = g_start[g + 1];
        float4 v = *(float4*)&stage[r * SPITCH + 4 * lane];
        for (int j = s; j < e_end; j++) {
            float* base = out + ((size_t)b * E_ + g_order[j]) * 512 + n0;
            *(float4*)(base + 4 * lane) = v;
        }
    }
}

// ---------------- per-group softmax-weighted reduction (fp16 EV, unroll-2) ----------------
__global__ __launch_bounds__(128)
void segreduce_k() {
    int g = blockIdx.x, b = blockIdx.y;
    int t = threadIdx.x;                 // t covers d = 4t..4t+3
    int s = g_start[g], e_end = g_start[g + 1];

    float4 den = make_float4(0.f, 0.f, 0.f, 0.f);
    float4 num = make_float4(0.f, 0.f, 0.f, 0.f);

    auto accum = [&](const __half2* row) {
        __half2 w01 = row[2 * t],       w23 = row[2 * t + 1];
        __half2 v01 = row[256 + 2 * t], v23 = row[256 + 2 * t + 1];
        float2 w0 = __half22float2(w01), w1 = __half22float2(w23);
        float2 x0 = __half22float2(v01), x1 = __half22float2(v23);
        den.x += w0.x; den.y += w0.y; den.z += w1.x; den.w += w1.y;
        num.x += w0.x * x0.x; num.y += w0.y * x0.y;
        num.z += w1.x * x1.x; num.w += w1.y * x1.y;
    };

    int j = s;
    for (; j + 2 <= e_end; j += 2) {     // MLP-2 over the random row reads
        int e0 = g_order[j], e1 = g_order[j + 1];
        const __half2* r0 = (const __half2*)(g_EV + ((size_t)b * E_ + e0) * 1024);
        const __half2* r1 = (const __half2*)(g_EV + ((size_t)b * E_ + e1) * 1024);
        accum(r0);
        accum(r1);
    }
    if (j < e_end) {
        int e0 = g_order[j];
        accum((const __half2*)(g_EV + ((size_t)b * E_ + e0) * 1024));
    }

    float y0 = (den.x > 0.f) ? num.x / den.x : 0.f;
    float y1 = (den.y > 0.f) ? num.y / den.y : 0.f;
    float y2 = (den.z > 0.f) ? num.z / den.z : 0.f;
    float y3 = (den.w > 0.f) ? num.w / den.w : 0.f;

    size_t o2 = ((size_t)b * G_ + g) * 256 + (size_t)t * 2;   // half2 index
    ((__half2*)g_y16)[o2]     = __floats2half2_rn(y0, y1);
    ((__half2*)g_y16)[o2 + 1] = __floats2half2_rn(y2, y3);
}

// ---------------- launcher -----------------------------------------------------------------
extern "C" void kernel_launch(void* const* d_in, const int* in_sizes, int n_in,
                              void* d_out, int out_size) {
    const float* x  = (const float*)d_in[0];
    const int*   ix = (const int*)d_in[1];
    const float* Wf = (const float*)d_in[2];
    const float* bf = (const float*)d_in[3];
    const float* Wg = (const float*)d_in[4];
    const float* bg = (const float*)d_in[5];
    const float* Wh = (const float*)d_in[6];
    const float* bh = (const float*)d_in[7];
    float* out = (float*)d_out;

    __half *wstk, *wh, *y16, *ev;
    cudaGetSymbolAddress((void**)&wstk, g_wstk);
    cudaGetSymbolAddress((void**)&wh, g_wh);
    cudaGetSymbolAddress((void**)&y16, g_y16);
    cudaGetSymbolAddress((void**)&ev, g_EV);
    float* pbstk;
    cudaGetSymbolAddress((void**)&pbstk, g_bstk);

    cudaFuncSetAttribute(gemm16_x, cudaFuncAttributeMaxDynamicSharedMemorySize, SMEM_X);
    cudaFuncSetAttribute(gemm16_y, cudaFuncAttributeMaxDynamicSharedMemorySize, SMEM_Y);

    const int T = 256;

    // launch 0: prep (weight cvts + bias + histogram)
    prep_k<<<897, T>>>(Wg, Wf, Wh, bg, bf, ix);
    // launches 1-2: CSR scan + scatter
    scan_k<<<1, 256>>>();
    scatter_k<<<E_ / T, T>>>(ix);
    // launch 3: projections (stacked) from fp32 x directly -> EV fp16
    {
        dim3 grid(4, (B_ * E_) / 128);
        gemm16_x<<<grid, 512, SMEM_X>>>(x, wstk, pbstk, ev, 1024);
    }
    // launch 4: per-group softmax-weighted reduce -> y16
    {
        dim3 grid(G_, B_);
        segreduce_k<<<grid, 128>>>();
    }
    // launch 5: of = y @ Wh^T + bh, scattered straight to out[b,e,:]
    {
        dim3 grid(4, (B_ * G_) / 64);
        gemm16_y<<<grid, 256, SMEM_Y>>>(y16, wh, bh, out);
    }
}